// round 7
// baseline (speedup 1.0000x reference)
#include <cuda_runtime.h>
#include <cuda_bf16.h>
#include <cstdint>
#include <cstddef>

#define N_NODES 40000
#define N_EDGES 640000
#define IN_F    256
#define EDGE_F  64
#define OUT_F   128
#define NH      8
#define DH      16

// ---------------- scratch ----------------
__device__ __align__(16) float g_Wh[(size_t)N_NODES * OUT_F];
__device__ __align__(16) float g_ssrc[N_NODES * NH];
__device__ __align__(16) float g_sdst[N_NODES * NH];
__device__ __align__(16) float g_sval[(size_t)N_EDGES * NH];   // CSR-ordered edge scores
__device__ __align__(16) int   g_ssidx[N_EDGES];               // CSR-ordered src ids
__device__ __align__(16) int   g_count[N_NODES];
__device__ __align__(16) int   g_rowstart[N_NODES + 1];
__device__ __align__(16) int   g_cursor[N_NODES];
__device__ float g_weff[NH * EDGE_F];
__device__ float g_beff[NH];

// ---------------- helpers ----------------
__device__ __forceinline__ uint32_t smem_u32(const void* p) {
    uint32_t a;
    asm("{ .reg .u64 t; cvta.to.shared.u64 t, %1; cvt.u32.u64 %0, t; }" : "=r"(a) : "l"(p));
    return a;
}
__device__ __forceinline__ uint32_t swz(uint32_t off) {
    return off ^ ((off >> 3) & 0x70);
}
__device__ __forceinline__ void ldsm4(uint32_t& r0, uint32_t& r1, uint32_t& r2, uint32_t& r3, uint32_t addr) {
    asm volatile("ldmatrix.sync.aligned.m8n8.x4.shared.b16 {%0,%1,%2,%3}, [%4];"
                 : "=r"(r0), "=r"(r1), "=r"(r2), "=r"(r3) : "r"(addr));
}
__device__ __forceinline__ void mma16816(float* c, uint32_t a0, uint32_t a1, uint32_t a2, uint32_t a3,
                                         uint32_t b0, uint32_t b1) {
    asm volatile("mma.sync.aligned.m16n8k16.row.col.f32.bf16.bf16.f32 "
                 "{%0,%1,%2,%3}, {%4,%5,%6,%7}, {%8,%9}, {%0,%1,%2,%3};"
                 : "+f"(c[0]), "+f"(c[1]), "+f"(c[2]), "+f"(c[3])
                 : "r"(a0), "r"(a1), "r"(a2), "r"(a3), "r"(b0), "r"(b1));
}
__device__ __forceinline__ uint32_t pack_bf16x2(float a, float b) {
    __nv_bfloat16 x = __float2bfloat16(a), y = __float2bfloat16(b);
    return (uint32_t)__bfloat16_as_ushort(x) | ((uint32_t)__bfloat16_as_ushort(y) << 16);
}

// ---------------- K0: dst histogram + fold attn into edge_w ----------------
__global__ void k_init(const int* __restrict__ dst,
                       const float* __restrict__ edge_w,
                       const float* __restrict__ edge_b,
                       const float* __restrict__ attn) {
    int e = blockIdx.x * blockDim.x + threadIdx.x;
    if (e < N_EDGES) atomicAdd(&g_count[dst[e]], 1);
    if (blockIdx.x == 0) {
        for (int i = threadIdx.x; i < NH * EDGE_F; i += blockDim.x) {
            int h = i >> 6, k = i & 63;
            float s = 0.f;
            #pragma unroll
            for (int d = 0; d < DH; d++)
                s += edge_w[(h * DH + d) * EDGE_F + k] * attn[h * 48 + 32 + d];
            g_weff[i] = s;
        }
        if (threadIdx.x < NH) {
            int h = threadIdx.x;
            float s = 0.f;
            #pragma unroll
            for (int d = 0; d < DH; d++)
                s += edge_b[h * DH + d] * attn[h * 48 + 32 + d];
            g_beff[h] = s;
        }
    }
}

// ---------------- K1: bf16-split MMA GEMM: Wh = A @ B^T + bias, fused s_src/s_dst ----------------
#define SMEM_GEMM 65536
__global__ __launch_bounds__(256) void k_gemm(const float* __restrict__ A,
                                              const float* __restrict__ B,
                                              const float* __restrict__ bias,
                                              const float* __restrict__ attn) {
    extern __shared__ char sm[];
    const uint32_t A_HI = 0, A_LO = 16384, B_HI = 32768, B_LO = 49152;
    uint32_t sbase = smem_u32(sm);

    int tid = threadIdx.x, w = tid >> 5, lane = tid & 31;
    int m0 = blockIdx.x * 128;
    int wm = (w >> 1) * 32, wn = (w & 1) * 64;
    int g = lane >> 2, t = lane & 3;

    float c[2][8][4];
    #pragma unroll
    for (int mt = 0; mt < 2; mt++)
        #pragma unroll
        for (int nt = 0; nt < 8; nt++)
            #pragma unroll
            for (int j = 0; j < 4; j++) c[mt][nt][j] = 0.f;

    #pragma unroll 1
    for (int chunk = 0; chunk < 4; chunk++) {
        int k0 = chunk << 6;
        #pragma unroll
        for (int i = 0; i < 8; i++) {
            int idx = tid + i * 256;
            int r = idx >> 4;
            int cc = (idx & 15) << 2;
            int m = m0 + r;
            float4 va = (m < N_NODES) ? *(const float4*)&A[(size_t)m * IN_F + k0 + cc]
                                      : make_float4(0.f, 0.f, 0.f, 0.f);
            float4 vb = *(const float4*)&B[(size_t)r * IN_F + k0 + cc];
            uint32_t o = swz((uint32_t)(r * 128 + cc * 2));
            {
                float h0 = __bfloat162float(__float2bfloat16(va.x));
                float h1 = __bfloat162float(__float2bfloat16(va.y));
                float h2 = __bfloat162float(__float2bfloat16(va.z));
                float h3 = __bfloat162float(__float2bfloat16(va.w));
                *(uint2*)(sm + A_HI + o) = make_uint2(pack_bf16x2(h0, h1), pack_bf16x2(h2, h3));
                *(uint2*)(sm + A_LO + o) = make_uint2(pack_bf16x2(va.x - h0, va.y - h1),
                                                      pack_bf16x2(va.z - h2, va.w - h3));
            }
            {
                float h0 = __bfloat162float(__float2bfloat16(vb.x));
                float h1 = __bfloat162float(__float2bfloat16(vb.y));
                float h2 = __bfloat162float(__float2bfloat16(vb.z));
                float h3 = __bfloat162float(__float2bfloat16(vb.w));
                *(uint2*)(sm + B_HI + o) = make_uint2(pack_bf16x2(h0, h1), pack_bf16x2(h2, h3));
                *(uint2*)(sm + B_LO + o) = make_uint2(pack_bf16x2(vb.x - h0, vb.y - h1),
                                                      pack_bf16x2(vb.z - h2, vb.w - h3));
            }
        }
        __syncthreads();

        int lr = lane & 15, lc = (lane >> 4) << 3;
        #pragma unroll
        for (int ks = 0; ks < 4; ks++) {
            int kk = (ks << 4) + lc;
            uint32_t ao0 = swz((uint32_t)((wm + lr) * 128 + kk * 2));
            uint32_t ao1 = swz((uint32_t)((wm + 16 + lr) * 128 + kk * 2));
            uint32_t ah[2][4], al[2][4];
            ldsm4(ah[0][0], ah[0][1], ah[0][2], ah[0][3], sbase + A_HI + ao0);
            ldsm4(ah[1][0], ah[1][1], ah[1][2], ah[1][3], sbase + A_HI + ao1);
            ldsm4(al[0][0], al[0][1], al[0][2], al[0][3], sbase + A_LO + ao0);
            ldsm4(al[1][0], al[1][1], al[1][2], al[1][3], sbase + A_LO + ao1);
            #pragma unroll
            for (int np = 0; np < 4; np++) {
                uint32_t bo = swz((uint32_t)((wn + np * 16 + lr) * 128 + kk * 2));
                uint32_t bh[4], bl[4];
                ldsm4(bh[0], bh[1], bh[2], bh[3], sbase + B_HI + bo);
                ldsm4(bl[0], bl[1], bl[2], bl[3], sbase + B_LO + bo);
                #pragma unroll
                for (int mt = 0; mt < 2; mt++) {
                    mma16816(c[mt][np * 2],     ah[mt][0], ah[mt][1], ah[mt][2], ah[mt][3], bh[0], bh[2]);
                    mma16816(c[mt][np * 2],     ah[mt][0], ah[mt][1], ah[mt][2], ah[mt][3], bl[0], bl[2]);
                    mma16816(c[mt][np * 2],     al[mt][0], al[mt][1], al[mt][2], al[mt][3], bh[0], bh[2]);
                    mma16816(c[mt][np * 2 + 1], ah[mt][0], ah[mt][1], ah[mt][2], ah[mt][3], bh[1], bh[3]);
                    mma16816(c[mt][np * 2 + 1], ah[mt][0], ah[mt][1], ah[mt][2], ah[mt][3], bl[1], bl[3]);
                    mma16816(c[mt][np * 2 + 1], al[mt][0], al[mt][1], al[mt][2], al[mt][3], bh[1], bh[3]);
                }
            }
        }
        __syncthreads();
    }

    // ---- epilogue ----
    float as0[8], as1[8], ad0[8], ad1[8], bb0[8], bb1[8];
    #pragma unroll
    for (int nt = 0; nt < 8; nt++) {
        int col = wn + nt * 8 + t * 2;
        int h = col >> 4, d = col & 15;
        as0[nt] = attn[h * 48 + d];      as1[nt] = attn[h * 48 + d + 1];
        ad0[nt] = attn[h * 48 + 16 + d]; ad1[nt] = attn[h * 48 + 16 + d + 1];
        bb0[nt] = bias[col];             bb1[nt] = bias[col + 1];
    }
    float ps[2][2][4], pd[2][2][4];
    #pragma unroll
    for (int mt = 0; mt < 2; mt++)
        #pragma unroll
        for (int hf = 0; hf < 2; hf++)
            #pragma unroll
            for (int hh = 0; hh < 4; hh++) { ps[mt][hf][hh] = 0.f; pd[mt][hf][hh] = 0.f; }

    #pragma unroll
    for (int mt = 0; mt < 2; mt++) {
        #pragma unroll
        for (int hf = 0; hf < 2; hf++) {
            int m = m0 + wm + mt * 16 + g + hf * 8;
            bool ok = (m < N_NODES);
            #pragma unroll
            for (int nt = 0; nt < 8; nt++) {
                float v0 = c[mt][nt][hf * 2 + 0] + bb0[nt];
                float v1 = c[mt][nt][hf * 2 + 1] + bb1[nt];
                if (ok) {
                    int col = wn + nt * 8 + t * 2;
                    *(float2*)&g_Wh[(size_t)m * OUT_F + col] = make_float2(v0, v1);
                }
                ps[mt][hf][nt >> 1] += v0 * as0[nt] + v1 * as1[nt];
                pd[mt][hf][nt >> 1] += v0 * ad0[nt] + v1 * ad1[nt];
            }
        }
    }
    #pragma unroll
    for (int mt = 0; mt < 2; mt++)
        #pragma unroll
        for (int hf = 0; hf < 2; hf++)
            #pragma unroll
            for (int hh = 0; hh < 4; hh++) {
                float s = ps[mt][hf][hh], d2 = pd[mt][hf][hh];
                s += __shfl_xor_sync(0xffffffffu, s, 1);
                s += __shfl_xor_sync(0xffffffffu, s, 2);
                d2 += __shfl_xor_sync(0xffffffffu, d2, 1);
                d2 += __shfl_xor_sync(0xffffffffu, d2, 2);
                if (t == 0) {
                    int m = m0 + wm + mt * 16 + g + hf * 8;
                    if (m < N_NODES) {
                        int h = (w & 1) * 4 + hh;
                        g_ssrc[m * NH + h] = s;
                        g_sdst[m * NH + h] = d2;
                    }
                }
            }
}

// ---------------- K2: single-phase exclusive scan ----------------
__global__ __launch_bounds__(1024) void k_scan() {
    __shared__ int wsum[32];
    int tid = threadIdx.x, lane = tid & 31, wid = tid >> 5;
    int base = tid * 40;
    int4 v[10];
    #pragma unroll
    for (int j = 0; j < 10; j++) {
        int o = base + j * 4;
        v[j] = (o < N_NODES) ? *(const int4*)&g_count[o] : make_int4(0, 0, 0, 0);
    }
    int t = 0;
    #pragma unroll
    for (int j = 0; j < 10; j++) t += v[j].x + v[j].y + v[j].z + v[j].w;
    int x = t;
    #pragma unroll
    for (int o = 1; o < 32; o <<= 1) {
        int y = __shfl_up_sync(0xffffffffu, x, o);
        if (lane >= o) x += y;
    }
    if (lane == 31) wsum[wid] = x;
    __syncthreads();
    if (wid == 0) {
        int wv = wsum[lane], xx = wv;
        #pragma unroll
        for (int o = 1; o < 32; o <<= 1) {
            int y = __shfl_up_sync(0xffffffffu, xx, o);
            if (lane >= o) xx += y;
        }
        wsum[lane] = xx - wv;
    }
    __syncthreads();
    int run = (x - t) + wsum[wid];
    #pragma unroll
    for (int j = 0; j < 10; j++) {
        int o = base + j * 4;
        int4 r;
        r.x = run; run += v[j].x;
        r.y = run; run += v[j].y;
        r.z = run; run += v[j].z;
        r.w = run; run += v[j].w;
        if (o < N_NODES) {
            *(int4*)&g_rowstart[o] = r;
            *(int4*)&g_cursor[o]   = r;
        }
    }
    if (tid == 1023) g_rowstart[N_NODES] = run;
}

// ---------------- K3: s_e cooperative (8 threads/edge) + s_src fold + CSR scatter ----------------
#define SE_BLOCKS 2048
__global__ __launch_bounds__(256) void k_se(const float* __restrict__ EF,
                                            const int* __restrict__ src,
                                            const int* __restrict__ dst) {
    __shared__ float ws[NH * EDGE_F];
    __shared__ float bs[NH];
    int tid = threadIdx.x;
    for (int i = tid; i < NH * EDGE_F; i += 256) ws[i] = g_weff[i];
    if (tid < NH) bs[tid] = g_beff[tid];
    __syncthreads();

    int lane = tid & 31;
    int t = lane & 7;                          // thread-in-edge-group
    int b4 = t & 4, b2 = t & 2, b1 = t & 1;
    int gwarp = (blockIdx.x * 256 + tid) >> 5;
    const int nwarps = SE_BLOCKS * 8;
    float bsv = bs[t];

    for (int e0 = gwarp * 4; e0 < N_EDGES; e0 += nwarps * 4) {
        int e = e0 + (lane >> 3);              // N_EDGES % 4 == 0 -> always valid
        const float* row = &EF[(size_t)e * EDGE_F + t * 8];
        float4 x0 = *(const float4*)row;
        float4 x1 = *(const float4*)(row + 4);
        float v8[8];
        #pragma unroll
        for (int h = 0; h < 8; h++) {
            float4 w0 = *(const float4*)&ws[h * 64 + t * 8];
            float4 w1 = *(const float4*)&ws[h * 64 + t * 8 + 4];
            v8[h] = x0.x * w0.x + x0.y * w0.y + x0.z * w0.z + x0.w * w0.w
                  + x1.x * w1.x + x1.y * w1.y + x1.z * w1.z + x1.w * w1.w;
        }
        // tree reduction: lane t ends with head t
        float v4[4];
        #pragma unroll
        for (int i = 0; i < 4; i++) {
            float snd = v8[(b4 ^ 4) + i];
            float rcv = __shfl_xor_sync(0xffffffffu, snd, 4);
            v4[i] = v8[b4 + i] + rcv;
        }
        float v2[2];
        #pragma unroll
        for (int j = 0; j < 2; j++) {
            float snd = v4[(b2 ^ 2) + j];
            float rcv = __shfl_xor_sync(0xffffffffu, snd, 2);
            v2[j] = v4[b2 + j] + rcv;
        }
        float snd = v2[b1 ^ 1];
        float rcv = __shfl_xor_sync(0xffffffffu, snd, 1);
        float sv = v2[b1] + rcv + bsv;

        int s = src[e];
        sv += g_ssrc[s * NH + t];
        int pos = 0;
        if (t == 0) pos = atomicAdd(&g_cursor[dst[e]], 1);
        pos = __shfl_sync(0xffffffffu, pos, lane & 24);
        g_sval[(size_t)pos * NH + t] = sv;
        if (t == 0) g_ssidx[pos] = s;
    }
}

// ---------------- K4: gather per node (warp/node), unrolled x2 ----------------
__global__ __launch_bounds__(256) void k_gather(float* __restrict__ out) {
    int warp = (blockIdx.x * blockDim.x + threadIdx.x) >> 5;
    int lane = threadIdx.x & 31;
    if (warp >= N_NODES) return;
    int h = lane >> 2;
    float sd = g_sdst[warp * NH + h];
    int beg = g_rowstart[warp], end = g_rowstart[warp + 1];
    float4 acc = make_float4(0.f, 0.f, 0.f, 0.f);
    float z = 0.f;
    int i = beg;
    for (; i + 2 <= end; i += 2) {
        int s0 = g_ssidx[i], s1 = g_ssidx[i + 1];
        float a0 = g_sval[(size_t)i * NH + h];
        float a1 = g_sval[(size_t)(i + 1) * NH + h];
        float4 w0 = *(const float4*)&g_Wh[(size_t)s0 * OUT_F + lane * 4];
        float4 w1 = *(const float4*)&g_Wh[(size_t)s1 * OUT_F + lane * 4];
        float e0 = a0 + sd; e0 = fmaxf(e0, 0.2f * e0);
        float e1 = a1 + sd; e1 = fmaxf(e1, 0.2f * e1);
        float x0 = __expf(e0), x1 = __expf(e1);
        z += x0 + x1;
        acc.x += x0 * w0.x + x1 * w1.x;
        acc.y += x0 * w0.y + x1 * w1.y;
        acc.z += x0 * w0.z + x1 * w1.z;
        acc.w += x0 * w0.w + x1 * w1.w;
    }
    if (i < end) {
        int s0 = g_ssidx[i];
        float a0 = g_sval[(size_t)i * NH + h];
        float4 w0 = *(const float4*)&g_Wh[(size_t)s0 * OUT_F + lane * 4];
        float e0 = a0 + sd; e0 = fmaxf(e0, 0.2f * e0);
        float x0 = __expf(e0);
        z += x0;
        acc.x += x0 * w0.x; acc.y += x0 * w0.y;
        acc.z += x0 * w0.z; acc.w += x0 * w0.w;
    }
    float4 o = make_float4(0.f, 0.f, 0.f, 0.f);
    if (end > beg) {
        float inv = 1.f / z;
        o = make_float4(acc.x * inv, acc.y * inv, acc.z * inv, acc.w * inv);
    }
    *(float4*)&out[(size_t)warp * OUT_F + lane * 4] = o;
}

// ---------------- launch ----------------
extern "C" void kernel_launch(void* const* d_in, const int* in_sizes, int n_in,
                              void* d_out, int out_size) {
    const float* node_feats = (const float*)d_in[0];
    const float* edge_feats = (const float*)d_in[1];
    const int*   src        = (const int*)d_in[2];
    const int*   dst        = (const int*)d_in[3];
    const float* node_w     = (const float*)d_in[4];
    const float* node_b     = (const float*)d_in[5];
    const float* edge_w     = (const float*)d_in[6];
    const float* edge_b     = (const float*)d_in[7];
    const float* attn       = (const float*)d_in[8];
    float* out = (float*)d_out;

    void* count_ptr = nullptr;
    cudaGetSymbolAddress(&count_ptr, g_count);
    cudaMemsetAsync(count_ptr, 0, N_NODES * sizeof(int));

    cudaFuncSetAttribute(k_gemm, cudaFuncAttributeMaxDynamicSharedMemorySize, SMEM_GEMM);

    k_init<<<(N_EDGES + 255) / 256, 256>>>(dst, edge_w, edge_b, attn);
    k_gemm<<<(N_NODES + 127) / 128, 256, SMEM_GEMM>>>(node_feats, node_w, node_b, attn);
    k_scan<<<1, 1024>>>();
    k_se<<<SE_BLOCKS, 256>>>(edge_feats, src, dst);
    k_gather<<<(N_NODES * 32 + 255) / 256, 256>>>(out);
}

// round 8
// speedup vs baseline: 1.4251x; 1.4251x over previous
#include <cuda_runtime.h>
#include <cuda_bf16.h>
#include <cstdint>
#include <cstddef>

#define N_NODES 40000
#define N_EDGES 640000
#define IN_F    256
#define EDGE_F  64
#define OUT_F   128
#define NH      8
#define DH      16

// ---------------- scratch ----------------
__device__ __align__(16) float g_Wh[(size_t)N_NODES * OUT_F];
__device__ __align__(16) float g_ssrc[N_NODES * NH];
__device__ __align__(16) float g_sdst[N_NODES * NH];
__device__ __align__(16) float g_sval[(size_t)N_EDGES * NH];   // CSR-ordered edge scores
__device__ __align__(16) int   g_ssidx[N_EDGES];               // CSR-ordered src ids
__device__ __align__(16) int   g_count[N_NODES];
__device__ __align__(16) int   g_rowstart[N_NODES + 1];
__device__ __align__(16) int   g_cursor[N_NODES];
__device__ float g_weff[NH * EDGE_F];
__device__ float g_beff[NH];

// ---------------- helpers ----------------
__device__ __forceinline__ uint32_t smem_u32(const void* p) {
    uint32_t a;
    asm("{ .reg .u64 t; cvta.to.shared.u64 t, %1; cvt.u32.u64 %0, t; }" : "=r"(a) : "l"(p));
    return a;
}
__device__ __forceinline__ uint32_t swz(uint32_t off) {
    return off ^ ((off >> 3) & 0x70);
}
__device__ __forceinline__ void ldsm4(uint32_t& r0, uint32_t& r1, uint32_t& r2, uint32_t& r3, uint32_t addr) {
    asm volatile("ldmatrix.sync.aligned.m8n8.x4.shared.b16 {%0,%1,%2,%3}, [%4];"
                 : "=r"(r0), "=r"(r1), "=r"(r2), "=r"(r3) : "r"(addr));
}
__device__ __forceinline__ void mma16816(float* c, uint32_t a0, uint32_t a1, uint32_t a2, uint32_t a3,
                                         uint32_t b0, uint32_t b1) {
    asm volatile("mma.sync.aligned.m16n8k16.row.col.f32.bf16.bf16.f32 "
                 "{%0,%1,%2,%3}, {%4,%5,%6,%7}, {%8,%9}, {%0,%1,%2,%3};"
                 : "+f"(c[0]), "+f"(c[1]), "+f"(c[2]), "+f"(c[3])
                 : "r"(a0), "r"(a1), "r"(a2), "r"(a3), "r"(b0), "r"(b1));
}
__device__ __forceinline__ uint32_t pack_bf16x2(float a, float b) {
    __nv_bfloat16 x = __float2bfloat16(a), y = __float2bfloat16(b);
    return (uint32_t)__bfloat16_as_ushort(x) | ((uint32_t)__bfloat16_as_ushort(y) << 16);
}

// ---------------- K0: dst histogram + fold attn into edge_w ----------------
__global__ void k_init(const int* __restrict__ dst,
                       const float* __restrict__ edge_w,
                       const float* __restrict__ edge_b,
                       const float* __restrict__ attn) {
    int e = blockIdx.x * blockDim.x + threadIdx.x;
    if (e < N_EDGES) atomicAdd(&g_count[dst[e]], 1);
    if (blockIdx.x == 0) {
        for (int i = threadIdx.x; i < NH * EDGE_F; i += blockDim.x) {
            int h = i >> 6, k = i & 63;
            float s = 0.f;
            #pragma unroll
            for (int d = 0; d < DH; d++)
                s += edge_w[(h * DH + d) * EDGE_F + k] * attn[h * 48 + 32 + d];
            g_weff[i] = s;
        }
        if (threadIdx.x < NH) {
            int h = threadIdx.x;
            float s = 0.f;
            #pragma unroll
            for (int d = 0; d < DH; d++)
                s += edge_b[h * DH + d] * attn[h * 48 + 32 + d];
            g_beff[h] = s;
        }
    }
}

// ---------------- K1: bf16-split MMA GEMM: Wh = A @ B^T + bias, fused s_src/s_dst ----------------
#define SMEM_GEMM 65536
__global__ __launch_bounds__(256) void k_gemm(const float* __restrict__ A,
                                              const float* __restrict__ B,
                                              const float* __restrict__ bias,
                                              const float* __restrict__ attn) {
    extern __shared__ char sm[];
    const uint32_t A_HI = 0, A_LO = 16384, B_HI = 32768, B_LO = 49152;
    uint32_t sbase = smem_u32(sm);

    int tid = threadIdx.x, w = tid >> 5, lane = tid & 31;
    int m0 = blockIdx.x * 128;
    int wm = (w >> 1) * 32, wn = (w & 1) * 64;
    int g = lane >> 2, t = lane & 3;

    float c[2][8][4];
    #pragma unroll
    for (int mt = 0; mt < 2; mt++)
        #pragma unroll
        for (int nt = 0; nt < 8; nt++)
            #pragma unroll
            for (int j = 0; j < 4; j++) c[mt][nt][j] = 0.f;

    #pragma unroll 1
    for (int chunk = 0; chunk < 4; chunk++) {
        int k0 = chunk << 6;
        #pragma unroll
        for (int i = 0; i < 8; i++) {
            int idx = tid + i * 256;
            int r = idx >> 4;
            int cc = (idx & 15) << 2;
            int m = m0 + r;
            float4 va = (m < N_NODES) ? *(const float4*)&A[(size_t)m * IN_F + k0 + cc]
                                      : make_float4(0.f, 0.f, 0.f, 0.f);
            float4 vb = *(const float4*)&B[(size_t)r * IN_F + k0 + cc];
            uint32_t o = swz((uint32_t)(r * 128 + cc * 2));
            {
                float h0 = __bfloat162float(__float2bfloat16(va.x));
                float h1 = __bfloat162float(__float2bfloat16(va.y));
                float h2 = __bfloat162float(__float2bfloat16(va.z));
                float h3 = __bfloat162float(__float2bfloat16(va.w));
                *(uint2*)(sm + A_HI + o) = make_uint2(pack_bf16x2(h0, h1), pack_bf16x2(h2, h3));
                *(uint2*)(sm + A_LO + o) = make_uint2(pack_bf16x2(va.x - h0, va.y - h1),
                                                      pack_bf16x2(va.z - h2, va.w - h3));
            }
            {
                float h0 = __bfloat162float(__float2bfloat16(vb.x));
                float h1 = __bfloat162float(__float2bfloat16(vb.y));
                float h2 = __bfloat162float(__float2bfloat16(vb.z));
                float h3 = __bfloat162float(__float2bfloat16(vb.w));
                *(uint2*)(sm + B_HI + o) = make_uint2(pack_bf16x2(h0, h1), pack_bf16x2(h2, h3));
                *(uint2*)(sm + B_LO + o) = make_uint2(pack_bf16x2(vb.x - h0, vb.y - h1),
                                                      pack_bf16x2(vb.z - h2, vb.w - h3));
            }
        }
        __syncthreads();

        int lr = lane & 15, lc = (lane >> 4) << 3;
        #pragma unroll
        for (int ks = 0; ks < 4; ks++) {
            int kk = (ks << 4) + lc;
            uint32_t ao0 = swz((uint32_t)((wm + lr) * 128 + kk * 2));
            uint32_t ao1 = swz((uint32_t)((wm + 16 + lr) * 128 + kk * 2));
            uint32_t ah[2][4], al[2][4];
            ldsm4(ah[0][0], ah[0][1], ah[0][2], ah[0][3], sbase + A_HI + ao0);
            ldsm4(ah[1][0], ah[1][1], ah[1][2], ah[1][3], sbase + A_HI + ao1);
            ldsm4(al[0][0], al[0][1], al[0][2], al[0][3], sbase + A_LO + ao0);
            ldsm4(al[1][0], al[1][1], al[1][2], al[1][3], sbase + A_LO + ao1);
            #pragma unroll
            for (int np = 0; np < 4; np++) {
                uint32_t bo = swz((uint32_t)((wn + np * 16 + lr) * 128 + kk * 2));
                uint32_t bh[4], bl[4];
                ldsm4(bh[0], bh[1], bh[2], bh[3], sbase + B_HI + bo);
                ldsm4(bl[0], bl[1], bl[2], bl[3], sbase + B_LO + bo);
                #pragma unroll
                for (int mt = 0; mt < 2; mt++) {
                    mma16816(c[mt][np * 2],     ah[mt][0], ah[mt][1], ah[mt][2], ah[mt][3], bh[0], bh[2]);
                    mma16816(c[mt][np * 2],     ah[mt][0], ah[mt][1], ah[mt][2], ah[mt][3], bl[0], bl[2]);
                    mma16816(c[mt][np * 2],     al[mt][0], al[mt][1], al[mt][2], al[mt][3], bh[0], bh[2]);
                    mma16816(c[mt][np * 2 + 1], ah[mt][0], ah[mt][1], ah[mt][2], ah[mt][3], bh[1], bh[3]);
                    mma16816(c[mt][np * 2 + 1], ah[mt][0], ah[mt][1], ah[mt][2], ah[mt][3], bl[1], bl[3]);
                    mma16816(c[mt][np * 2 + 1], al[mt][0], al[mt][1], al[mt][2], al[mt][3], bh[1], bh[3]);
                }
            }
        }
        __syncthreads();
    }

    // ---- epilogue ----
    float as0[8], as1[8], ad0[8], ad1[8], bb0[8], bb1[8];
    #pragma unroll
    for (int nt = 0; nt < 8; nt++) {
        int col = wn + nt * 8 + t * 2;
        int h = col >> 4, d = col & 15;
        as0[nt] = attn[h * 48 + d];      as1[nt] = attn[h * 48 + d + 1];
        ad0[nt] = attn[h * 48 + 16 + d]; ad1[nt] = attn[h * 48 + 16 + d + 1];
        bb0[nt] = bias[col];             bb1[nt] = bias[col + 1];
    }
    float ps[2][2][4], pd[2][2][4];
    #pragma unroll
    for (int mt = 0; mt < 2; mt++)
        #pragma unroll
        for (int hf = 0; hf < 2; hf++)
            #pragma unroll
            for (int hh = 0; hh < 4; hh++) { ps[mt][hf][hh] = 0.f; pd[mt][hf][hh] = 0.f; }

    #pragma unroll
    for (int mt = 0; mt < 2; mt++) {
        #pragma unroll
        for (int hf = 0; hf < 2; hf++) {
            int m = m0 + wm + mt * 16 + g + hf * 8;
            bool ok = (m < N_NODES);
            #pragma unroll
            for (int nt = 0; nt < 8; nt++) {
                float v0 = c[mt][nt][hf * 2 + 0] + bb0[nt];
                float v1 = c[mt][nt][hf * 2 + 1] + bb1[nt];
                if (ok) {
                    int col = wn + nt * 8 + t * 2;
                    *(float2*)&g_Wh[(size_t)m * OUT_F + col] = make_float2(v0, v1);
                }
                ps[mt][hf][nt >> 1] += v0 * as0[nt] + v1 * as1[nt];
                pd[mt][hf][nt >> 1] += v0 * ad0[nt] + v1 * ad1[nt];
            }
        }
    }
    #pragma unroll
    for (int mt = 0; mt < 2; mt++)
        #pragma unroll
        for (int hf = 0; hf < 2; hf++)
            #pragma unroll
            for (int hh = 0; hh < 4; hh++) {
                float s = ps[mt][hf][hh], d2 = pd[mt][hf][hh];
                s += __shfl_xor_sync(0xffffffffu, s, 1);
                s += __shfl_xor_sync(0xffffffffu, s, 2);
                d2 += __shfl_xor_sync(0xffffffffu, d2, 1);
                d2 += __shfl_xor_sync(0xffffffffu, d2, 2);
                if (t == 0) {
                    int m = m0 + wm + mt * 16 + g + hf * 8;
                    if (m < N_NODES) {
                        int h = (w & 1) * 4 + hh;
                        g_ssrc[m * NH + h] = s;
                        g_sdst[m * NH + h] = d2;
                    }
                }
            }
}

// ---------------- K2: single-phase exclusive scan ----------------
__global__ __launch_bounds__(1024) void k_scan() {
    __shared__ int wsum[32];
    int tid = threadIdx.x, lane = tid & 31, wid = tid >> 5;
    int base = tid * 40;
    int4 v[10];
    #pragma unroll
    for (int j = 0; j < 10; j++) {
        int o = base + j * 4;
        v[j] = (o < N_NODES) ? *(const int4*)&g_count[o] : make_int4(0, 0, 0, 0);
    }
    int t = 0;
    #pragma unroll
    for (int j = 0; j < 10; j++) t += v[j].x + v[j].y + v[j].z + v[j].w;
    int x = t;
    #pragma unroll
    for (int o = 1; o < 32; o <<= 1) {
        int y = __shfl_up_sync(0xffffffffu, x, o);
        if (lane >= o) x += y;
    }
    if (lane == 31) wsum[wid] = x;
    __syncthreads();
    if (wid == 0) {
        int wv = wsum[lane], xx = wv;
        #pragma unroll
        for (int o = 1; o < 32; o <<= 1) {
            int y = __shfl_up_sync(0xffffffffu, xx, o);
            if (lane >= o) xx += y;
        }
        wsum[lane] = xx - wv;
    }
    __syncthreads();
    int run = (x - t) + wsum[wid];
    #pragma unroll
    for (int j = 0; j < 10; j++) {
        int o = base + j * 4;
        int4 r;
        r.x = run; run += v[j].x;
        r.y = run; run += v[j].y;
        r.z = run; run += v[j].z;
        r.w = run; run += v[j].w;
        if (o < N_NODES) {
            *(int4*)&g_rowstart[o] = r;
            *(int4*)&g_cursor[o]   = r;
        }
    }
    if (tid == 1023) g_rowstart[N_NODES] = run;
}

// ---------------- K3: s_e cooperative (4 threads/edge, static regs) + CSR scatter ----------------
__global__ __launch_bounds__(256) void k_se(const float* __restrict__ EF,
                                            const int* __restrict__ src,
                                            const int* __restrict__ dst) {
    __shared__ float ws[NH * EDGE_F];
    __shared__ float bs[NH];
    int tid = threadIdx.x;
    for (int i = tid; i < NH * EDGE_F; i += 256) ws[i] = g_weff[i];
    if (tid < NH) bs[tid] = g_beff[tid];
    __syncthreads();

    int lane = tid & 31;
    int t = lane & 3;                          // lane-in-edge group
    int e = blockIdx.x * 64 + (tid >> 5) * 8 + (lane >> 2);   // 8 edges per warp

    // interleaved load: lane t covers k = t*4 + i*16  (group reads contiguous 64B per i)
    float4 x0 = *(const float4*)&EF[(size_t)e * EDGE_F + t * 4];
    float4 x1 = *(const float4*)&EF[(size_t)e * EDGE_F + t * 4 + 16];
    float4 x2 = *(const float4*)&EF[(size_t)e * EDGE_F + t * 4 + 32];
    float4 x3 = *(const float4*)&EF[(size_t)e * EDGE_F + t * 4 + 48];

    float acc[NH];
    #pragma unroll
    for (int h = 0; h < NH; h++) {
        const float* wr = &ws[h * EDGE_F + t * 4];
        float4 w0 = *(const float4*)wr;
        float4 w1 = *(const float4*)(wr + 16);
        float4 w2 = *(const float4*)(wr + 32);
        float4 w3 = *(const float4*)(wr + 48);
        acc[h] = x0.x * w0.x + x0.y * w0.y + x0.z * w0.z + x0.w * w0.w
               + x1.x * w1.x + x1.y * w1.y + x1.z * w1.z + x1.w * w1.w
               + x2.x * w2.x + x2.y * w2.y + x2.z * w2.z + x2.w * w2.w
               + x3.x * w3.x + x3.y * w3.y + x3.z * w3.z + x3.w * w3.w;
    }
    // butterfly reduce across the 4-lane group: all lanes end with full sums (static idx)
    #pragma unroll
    for (int h = 0; h < NH; h++) {
        acc[h] += __shfl_xor_sync(0xffffffffu, acc[h], 1);
        acc[h] += __shfl_xor_sync(0xffffffffu, acc[h], 2);
    }

    int s = 0, pos = 0;
    if (t == 0) {
        s = src[e];
        pos = atomicAdd(&g_cursor[dst[e]], 1);
    }
    int leader = lane & 28;
    s   = __shfl_sync(0xffffffffu, s, leader);
    pos = __shfl_sync(0xffffffffu, pos, leader);

    if (t < 2) {
        float4 sr = *(const float4*)&g_ssrc[s * NH + t * 4];
        float4 o;
        if (t == 0) {
            o = make_float4(acc[0] + bs[0] + sr.x, acc[1] + bs[1] + sr.y,
                            acc[2] + bs[2] + sr.z, acc[3] + bs[3] + sr.w);
        } else {
            o = make_float4(acc[4] + bs[4] + sr.x, acc[5] + bs[5] + sr.y,
                            acc[6] + bs[6] + sr.z, acc[7] + bs[7] + sr.w);
        }
        *(float4*)&g_sval[(size_t)pos * NH + t * 4] = o;
    }
    if (t == 0) g_ssidx[pos] = s;
}

// ---------------- K4: gather per node (warp/node), unrolled x2 ----------------
__global__ __launch_bounds__(256) void k_gather(float* __restrict__ out) {
    int warp = (blockIdx.x * blockDim.x + threadIdx.x) >> 5;
    int lane = threadIdx.x & 31;
    if (warp >= N_NODES) return;
    int h = lane >> 2;
    float sd = g_sdst[warp * NH + h];
    int beg = g_rowstart[warp], end = g_rowstart[warp + 1];
    float4 acc = make_float4(0.f, 0.f, 0.f, 0.f);
    float z = 0.f;
    int i = beg;
    for (; i + 2 <= end; i += 2) {
        int s0 = g_ssidx[i], s1 = g_ssidx[i + 1];
        float a0 = g_sval[(size_t)i * NH + h];
        float a1 = g_sval[(size_t)(i + 1) * NH + h];
        float4 w0 = *(const float4*)&g_Wh[(size_t)s0 * OUT_F + lane * 4];
        float4 w1 = *(const float4*)&g_Wh[(size_t)s1 * OUT_F + lane * 4];
        float e0 = a0 + sd; e0 = fmaxf(e0, 0.2f * e0);
        float e1 = a1 + sd; e1 = fmaxf(e1, 0.2f * e1);
        float x0 = __expf(e0), x1 = __expf(e1);
        z += x0 + x1;
        acc.x += x0 * w0.x + x1 * w1.x;
        acc.y += x0 * w0.y + x1 * w1.y;
        acc.z += x0 * w0.z + x1 * w1.z;
        acc.w += x0 * w0.w + x1 * w1.w;
    }
    if (i < end) {
        int s0 = g_ssidx[i];
        float a0 = g_sval[(size_t)i * NH + h];
        float4 w0 = *(const float4*)&g_Wh[(size_t)s0 * OUT_F + lane * 4];
        float e0 = a0 + sd; e0 = fmaxf(e0, 0.2f * e0);
        float x0 = __expf(e0);
        z += x0;
        acc.x += x0 * w0.x; acc.y += x0 * w0.y;
        acc.z += x0 * w0.z; acc.w += x0 * w0.w;
    }
    float4 o = make_float4(0.f, 0.f, 0.f, 0.f);
    if (end > beg) {
        float inv = 1.f / z;
        o = make_float4(acc.x * inv, acc.y * inv, acc.z * inv, acc.w * inv);
    }
    *(float4*)&out[(size_t)warp * OUT_F + lane * 4] = o;
}

// ---------------- launch ----------------
extern "C" void kernel_launch(void* const* d_in, const int* in_sizes, int n_in,
                              void* d_out, int out_size) {
    const float* node_feats = (const float*)d_in[0];
    const float* edge_feats = (const float*)d_in[1];
    const int*   src        = (const int*)d_in[2];
    const int*   dst        = (const int*)d_in[3];
    const float* node_w     = (const float*)d_in[4];
    const float* node_b     = (const float*)d_in[5];
    const float* edge_w     = (const float*)d_in[6];
    const float* edge_b     = (const float*)d_in[7];
    const float* attn       = (const float*)d_in[8];
    float* out = (float*)d_out;

    void* count_ptr = nullptr;
    cudaGetSymbolAddress(&count_ptr, g_count);
    cudaMemsetAsync(count_ptr, 0, N_NODES * sizeof(int));

    cudaFuncSetAttribute(k_gemm, cudaFuncAttributeMaxDynamicSharedMemorySize, SMEM_GEMM);

    k_init<<<(N_EDGES + 255) / 256, 256>>>(dst, edge_w, edge_b, attn);
    k_gemm<<<(N_NODES + 127) / 128, 256, SMEM_GEMM>>>(node_feats, node_w, node_b, attn);
    k_scan<<<1, 1024>>>();
    k_se<<<N_EDGES / 64, 256>>>(edge_feats, src, dst);
    k_gather<<<(N_NODES * 32 + 255) / 256, 256>>>(out);
}